// round 11
// baseline (speedup 1.0000x reference)
#include <cuda_runtime.h>
#include <cstdint>

#define NUM_CLASSES 100000
#define FEAT_DIM    128
#define BATCH       16384
#define LOSS_WEIGHT 0.01f
#define TOTAL       (NUM_CLASSES * FEAT_DIM)      // 12,800,000

#define K4_WARPS   8
#define K4_SPW     4
#define SPB        (K4_WARPS * K4_SPW)            // 32 samples per block
#define K4_THREADS (K4_WARPS * 32)
#define SCATTER_BLOCKS (BATCH / SPB)              // 512

// Zerofill: shifted float4 vectors over grad (= out+1, 4B-aligned):
// element e is 16B-aligned iff e ≡ 3 (mod 4); vectors cover [3, 3+4*K3_NV).
#define K3_NV ((TOTAL - 3) / 4)                   // 3,199,999
#define ZF_VPT 4                                  // float4 per thread
#define ZF_VPB (256 * ZF_VPT)                     // 1024 vectors per block
#define ZF_BLOCKS ((K3_NV + 1 + ZF_VPB - 1) / ZF_VPB)   // 3126

// k_hit: 4 slots per warp, 8 warps per block
#define HIT_SPW    4
#define HIT_BLOCKS (BATCH / (8 * HIT_SPW))        // 512

// Static scratch — zero-initialized at load; every call restores the
// zero-invariant on exactly what it touched (graph-replay safe).
__device__ float g_counts[NUM_CLASSES];
__device__ __align__(16) float g_featsum[TOTAL];  // raw per-class feat sums
__device__ int   g_hitlist[BATCH];                // c+1, densely packed; 0=empty
__device__ int   g_nhit;                          // append cursor
__device__ float g_loss;                          // loss accumulator

// ---------------------------------------------------------------------------
// K_main:
//   blocks [0, 512):   histogram (+first-toucher worklist) + featsum scatter
//                      + loss partial (RED into g_loss)
//   blocks [512, ...): branch-free zero-fill of grad (streaming float4)
// Disjoint writes: scatter -> counts/featsum/hitlist/g_loss; zerofill -> grad.
// ---------------------------------------------------------------------------
__global__ void __launch_bounds__(K4_THREADS)
k_main(const void* __restrict__ y,
       const float* __restrict__ feat,
       const float* __restrict__ centers,
       float* __restrict__ grad) {
    if (blockIdx.x >= SCATTER_BLOCKS) {
        // ---- zero-fill path: contiguous streaming stores ----
        int vbase = (blockIdx.x - SCATTER_BLOCKS) * ZF_VPB;
        const float4 z = make_float4(0.f, 0.f, 0.f, 0.f);
        #pragma unroll
        for (int k = 0; k < ZF_VPT; k++) {
            int j = vbase + k * 256 + threadIdx.x;
            if (j < K3_NV)
                __stcs(reinterpret_cast<float4*>(grad + 4 * j + 3), z);
        }
        if (vbase + threadIdx.x == K3_NV) {   // head (elems 0..2) + tail
            grad[0] = 0.0f; grad[1] = 0.0f; grad[2] = 0.0f;
            grad[TOTAL - 1] = 0.0f;
        }
        return;
    }

    // ---- scatter path ----
    int wid  = threadIdx.x >> 5;
    int lane = threadIdx.x & 31;
    int base = blockIdx.x * SPB + wid * K4_SPW;

    // Label dtype probe on a FIXED in-bounds range: odd 32-bit words of the
    // first 32 int64-slots (indices 1..63). int64 labels (<2^31) -> all zero;
    // int32 -> these are real labels, P(all zero) ~ 1e-160.
    __shared__ int s_is64;
    if (threadIdx.x < 32) {
        int odd = ((const int*)y)[2 * threadIdx.x + 1];
        unsigned b = __ballot_sync(0xFFFFFFFFu, odd != 0);
        if (threadIdx.x == 0) s_is64 = (b == 0u) ? 1 : 0;
    }
    __syncthreads();
    int is64 = s_is64;

    int c[K4_SPW];
    if (!is64) {
        int4 L = reinterpret_cast<const int4*>((const int*)y + base)[0];
        c[0] = L.x; c[1] = L.y; c[2] = L.z; c[3] = L.w;
    } else {
        const longlong2* y2 = reinterpret_cast<const longlong2*>(y);
        longlong2 a = y2[base / 2], b = y2[base / 2 + 1];
        c[0] = (int)a.x; c[1] = (int)a.y; c[2] = (int)b.x; c[3] = (int)b.y;
    }

    // histogram + first-toucher worklist (one lane per sample)
    if (lane < K4_SPW) {
        float old = atomicAdd(&g_counts[c[lane]], 1.0f);
        if (old == 0.0f) {
            int pos = atomicAdd(&g_nhit, 1);
            g_hitlist[pos] = c[lane] + 1;
        }
    }

    // Front-batch all 8 float4 loads (feat + centers rows).
    float4 f4[K4_SPW], e4[K4_SPW];
    #pragma unroll
    for (int s = 0; s < K4_SPW; s++)
        f4[s] = reinterpret_cast<const float4*>(feat + (base + s) * FEAT_DIM)[lane];
    #pragma unroll
    for (int s = 0; s < K4_SPW; s++)
        e4[s] = reinterpret_cast<const float4*>(centers + c[s] * FEAT_DIM)[lane];

    // featsum[c,:] += feat[i,:]  (vector RED, aligned scratch)
    #pragma unroll
    for (int s = 0; s < K4_SPW; s++) {
        float* dst = g_featsum + c[s] * FEAT_DIM + lane * 4;
        asm volatile("red.global.add.v4.f32 [%0], {%1, %2, %3, %4};"
                     :: "l"(dst), "f"(f4[s].x), "f"(f4[s].y),
                        "f"(f4[s].z), "f"(f4[s].w) : "memory");
    }

    float v = 0.0f;
    #pragma unroll
    for (int s = 0; s < K4_SPW; s++) {
        float d;
        d = f4[s].x - e4[s].x; v += d * d;
        d = f4[s].y - e4[s].y; v += d * d;
        d = f4[s].z - e4[s].z; v += d * d;
        d = f4[s].w - e4[s].w; v += d * d;
    }

    #pragma unroll
    for (int o = 16; o > 0; o >>= 1)
        v += __shfl_down_sync(0xFFFFFFFFu, v, o);

    __shared__ float s_part[K4_WARPS];
    if (lane == 0) s_part[wid] = v;
    __syncthreads();
    if (threadIdx.x == 0) {
        float t = 0.0f;
        #pragma unroll
        for (int w = 0; w < K4_WARPS; w++) t += s_part[w];
        asm volatile("red.global.add.f32 [%0], %1;"
                     :: "l"(&g_loss), "f"(t) : "memory");
    }
}

// ---------------------------------------------------------------------------
// K_hit: 4 slots per warp, phase-batched loads (4 hitlist -> 4 counts ->
// 8 row-float4s all independent in each phase).
//   grad[c,:] = ratio*centers[c,:] - featsum[c,:]/(1+cnt)
// then self-reset featsum rows, counts, hitlist slots (zero-invariant).
// Hitlist is densely packed, so tail warps exit on one branch. Empty slots
// use c=0 for the batched loads (results discarded; read-write races with
// the warp that owns row 0 are benign).
// ---------------------------------------------------------------------------
__global__ void __launch_bounds__(256)
k_hit(const float* __restrict__ centers,
      float* __restrict__ grad,
      float* __restrict__ loss_out) {
    if (blockIdx.x == 0 && threadIdx.x == 0) {
        *loss_out = LOSS_WEIGHT * 0.5f * g_loss;
        g_loss = 0.0f;
        g_nhit = 0;          // nobody in this kernel reads g_nhit
    }

    int wid  = threadIdx.x >> 5;
    int lane = threadIdx.x & 31;
    int slotBase = (blockIdx.x * 8 + wid) * HIT_SPW;

    // Phase 1: 4 independent hitlist loads
    int e[HIT_SPW];
    #pragma unroll
    for (int s = 0; s < HIT_SPW; s++)
        e[s] = g_hitlist[slotBase + s];
    if ((e[0] | e[1] | e[2] | e[3]) == 0) return;   // dense list: tail warps

    int c[HIT_SPW];
    #pragma unroll
    for (int s = 0; s < HIT_SPW; s++)
        c[s] = (e[s] > 0) ? (e[s] - 1) : 0;

    // Phase 2: 4 independent counts loads
    float cnt[HIT_SPW];
    #pragma unroll
    for (int s = 0; s < HIT_SPW; s++)
        cnt[s] = g_counts[c[s]];

    // Phase 3: 8 independent row loads (featsum + centers)
    float4 fs[HIT_SPW], ce[HIT_SPW];
    #pragma unroll
    for (int s = 0; s < HIT_SPW; s++)
        fs[s] = reinterpret_cast<const float4*>(g_featsum + c[s] * FEAT_DIM)[lane];
    #pragma unroll
    for (int s = 0; s < HIT_SPW; s++)
        ce[s] = __ldg(reinterpret_cast<const float4*>(centers + c[s] * FEAT_DIM) + lane);

    // Phase 4: compute + predicated stores
    #pragma unroll
    for (int s = 0; s < HIT_SPW; s++) {
        if (e[s] > 0) {
            float inv = 1.0f / (1.0f + cnt[s]);
            float r   = cnt[s] * inv;
            float* g = grad + c[s] * FEAT_DIM + lane * 4;
            g[0] = r * ce[s].x - inv * fs[s].x;
            g[1] = r * ce[s].y - inv * fs[s].y;
            g[2] = r * ce[s].z - inv * fs[s].z;
            g[3] = r * ce[s].w - inv * fs[s].w;
            reinterpret_cast<float4*>(g_featsum + c[s] * FEAT_DIM)[lane] =
                make_float4(0.f, 0.f, 0.f, 0.f);
        }
    }
    if (lane == 0) {
        #pragma unroll
        for (int s = 0; s < HIT_SPW; s++) {
            if (e[s] > 0) {
                g_counts[c[s]] = 0.0f;
                g_hitlist[slotBase + s] = 0;
            }
        }
    }
}

// ---------------------------------------------------------------------------
extern "C" void kernel_launch(void* const* d_in, const int* in_sizes, int n_in,
                              void* d_out, int out_size) {
    const void*  y       = d_in[0];
    const float* feat    = (const float*)d_in[1];
    const float* centers = (const float*)d_in[2];

    float* out      = (float*)d_out;
    float* loss_out = out;          // output 0: scalar loss
    float* grad     = out + 1;      // output 1: [C, D] grad (4B-aligned only!)

    // K_main: scatter (512 blocks) || zero-fill grad (3126 blocks)
    k_main<<<SCATTER_BLOCKS + ZF_BLOCKS, K4_THREADS>>>(y, feat, centers, grad);

    // K_hit: finalize hit rows (4 rows/warp) + loss; self-reset scratch
    k_hit<<<HIT_BLOCKS, 256>>>(centers, grad, loss_out);
}